// round 2
// baseline (speedup 1.0000x reference)
#include <cuda_runtime.h>

#define HH 1080
#define WW 1920
#define NPIX (HH * WW)
#define TX 32
#define TY 8
#define HALO 7
#define SW (TX + 2 * HALO)   // 46
#define SH (TY + 2 * HALO)   // 22
#define EPSF 1e-4f
#define LOG2E 1.4426950408889634f

// Scratch: SoA repack of the 11-channel input.
// g_nrmz[i]  = {nx, ny, nz, z}
// g_coldz[i] = {r,  g,  b,  dz}
__device__ float4 g_nrmz[NPIX];
__device__ float4 g_coldz[NPIX];

__global__ void prep_kernel(const float* __restrict__ in) {
    int i = blockIdx.x * blockDim.x + threadIdx.x;
    if (i >= NPIX) return;
    const float* p = in + (size_t)i * 11;
    g_nrmz[i]  = make_float4(p[3], p[4], p[5], p[9]);
    g_coldz[i] = make_float4(p[0], p[1], p[2], p[10]);
}

__device__ __forceinline__ float ex2f(float x) {
    float r;
    asm("ex2.approx.ftz.f32 %0, %1;" : "=f"(r) : "f"(x));
    return r;
}

__global__ void __launch_bounds__(TX * TY) filter_kernel(float* __restrict__ out) {
    __shared__ float4 s_nz[SH][SW];
    __shared__ float4 s_cd[SH][SW];

    const int bx = blockIdx.x * TX;
    const int by = blockIdx.y * TY;
    const int tid = threadIdx.y * TX + threadIdx.x;

    // Cooperative tile load with zero-filled halo.
    // Zero normals -> dot=0 -> clamp to 1e-4 -> ^128 underflows to exactly 0
    // -> w = 0, which reproduces the reference's bounds mask exactly.
    for (int idx = tid; idx < SH * SW; idx += TX * TY) {
        int sy = idx / SW;
        int sx = idx - sy * SW;
        int gy = by + sy - HALO;
        int gx = bx + sx - HALO;
        float4 a = make_float4(0.f, 0.f, 0.f, 0.f);
        float4 b = make_float4(0.f, 0.f, 0.f, 0.f);
        if ((unsigned)gy < (unsigned)HH && (unsigned)gx < (unsigned)WW) {
            int g = gy * WW + gx;
            a = g_nrmz[g];
            b = g_coldz[g];
        }
        s_nz[sy][sx] = a;
        s_cd[sy][sx] = b;
    }
    __syncthreads();

    const int lx = threadIdx.x;
    const int ly = threadIdx.y;

    const float4 cn = s_nz[ly + HALO][lx + HALO];
    const float4 cc = s_cd[ly + HALO][lx + HALO];
    const float nx = cn.x, ny = cn.y, nz = cn.z, z = cn.w;
    const float dz = cc.w;
    // Only used when dz*dist >= EPS, i.e. dz strictly positive there.
    const float rdz = __fdividef(1.0f, dz);

    float ar = 0.f, ag = 0.f, ab = 0.f, aw = 0.f;

#pragma unroll 1
    for (int dy = 0; dy < 15; ++dy) {
        const float4* pn = &s_nz[ly + dy][lx];
        const float4* pc = &s_cd[ly + dy][lx];
        const float dyf = (float)(dy - HALO);
        const float dy2 = dyf * dyf;
#pragma unroll
        for (int dx = 0; dx < 15; ++dx) {
            const float dx2 = (float)((dx - HALO) * (dx - HALO));
            const float4 n4 = pn[dx];
            const float4 c4 = pc[dx];

            // Geometric weight constants (dx2 is a literal after unroll).
            const float d2 = dy2 + dx2;              // dist^2
            const float rdist = rsqrtf(d2);          // +inf at center tap (selected away)
            const float cexp = d2 * (-0.5f * LOG2E); // log2(w_xy)

            // Normal weight: clamp(dot, eps, 1)^128 via 7 squarings.
            float d = n4.x * nx;
            d = fmaf(n4.y, ny, d);
            d = fmaf(n4.z, nz, d);
            d = fminf(fmaxf(d, EPSF), 1.0f);
            float q = d * d;      // ^2
            q = q * q;            // ^4
            q = q * q;            // ^8
            q = q * q;            // ^16
            q = q * q;            // ^32
            q = q * q;            // ^64
            const float wn = q * q; // ^128

            // Depth weight: exp(-|dz_tap|/max(dz*dist, EPS)),
            // branch-free: dz*dist >= EPS  <=>  dz >= EPS*rdist  (dist > 0),
            // continuous at the boundary (both branches equal there).
            const float dzt = n4.w - z;
            const float th = EPSF * rdist;
            const float inv = (dz >= th) ? (rdz * rdist) : 1e4f;
            const float t = fabsf(dzt) * inv;

            // w_xy * w_depth in a single ex2, then * wn.
            const float earg = fmaf(t, -LOG2E, cexp);
            const float w = ex2f(earg) * wn;

            aw += w;
            ar = fmaf(c4.x, w, ar);
            ag = fmaf(c4.y, w, ag);
            ab = fmaf(c4.z, w, ab);
        }
    }

    const float rw = __fdividef(1.0f, fmaxf(aw, EPSF));
    const int o = ((by + ly) * WW + (bx + lx)) * 3;
    out[o + 0] = ar * rw;
    out[o + 1] = ag * rw;
    out[o + 2] = ab * rw;
}

extern "C" void kernel_launch(void* const* d_in, const int* in_sizes, int n_in,
                              void* d_out, int out_size) {
    const float* in = (const float*)d_in[0];
    float* out = (float*)d_out;
    (void)in_sizes; (void)n_in; (void)out_size;

    prep_kernel<<<(NPIX + 255) / 256, 256>>>(in);

    dim3 grid(WW / TX, HH / TY);   // 60 x 135, exact
    dim3 block(TX, TY);
    filter_kernel<<<grid, block>>>(out);
}